// round 1
// baseline (speedup 1.0000x reference)
#include <cuda_runtime.h>
#include <cuda_bf16.h>

// Problem constants
#define B   8
#define HIN 256
#define WIN 256
#define C   64
#define HP  64      // pooled H (SAME, stride 4)
#define WP  64
#define POOL 6
#define STRIDE 4

// 8 MB pooled intermediate — static device scratch (no allocations allowed)
__device__ float g_pooled[B * HP * WP * C];

// ---------------------------------------------------------------------------
// Kernel 1: SAME avg-pool 6x6 stride 4.
// pad_total = (64-1)*4 + 6 - 256 = 2 -> pad_lo = 1, pad_hi = 1.
// Window for output oy covers input rows [oy*4 - 1, oy*4 + 5), clipped.
// avg = sum(valid) / count(valid), counts separable (cr*cc).
// One thread = one output pixel x 4 channels (float4).
// ---------------------------------------------------------------------------
__global__ __launch_bounds__(256) void pool_kernel(const float* __restrict__ in,
                                                   float* __restrict__ pooled) {
    int tid = blockIdx.x * blockDim.x + threadIdx.x;   // 0 .. B*HP*WP*16-1
    int c4 = tid & 15;
    int t  = tid >> 4;
    int ox = t & (WP - 1); t >>= 6;
    int oy = t & (HP - 1); t >>= 6;
    int b  = t;                                        // 0..7

    int r0 = oy * STRIDE - 1;
    int cc0 = ox * STRIDE - 1;
    int rlo = r0  < 0 ? 0 : r0;
    int rhi = r0 + POOL > HIN ? HIN : r0 + POOL;
    int clo = cc0 < 0 ? 0 : cc0;
    int chi = cc0 + POOL > WIN ? WIN : cc0 + POOL;

    const float* base = in + ((size_t)b * HIN * WIN) * C + c4 * 4;

    float4 s = make_float4(0.f, 0.f, 0.f, 0.f);
    #pragma unroll 1
    for (int r = rlo; r < rhi; ++r) {
        const float* rowp = base + (size_t)r * WIN * C;
        #pragma unroll 1
        for (int c = clo; c < chi; ++c) {
            float4 v = *reinterpret_cast<const float4*>(rowp + (size_t)c * C);
            s.x += v.x; s.y += v.y; s.z += v.z; s.w += v.w;
        }
    }

    float inv = 1.0f / (float)((rhi - rlo) * (chi - clo));
    float4 o = make_float4(s.x * inv, s.y * inv, s.z * inv, s.w * inv);
    // pooled index ((b*HP+oy)*WP+ox)*C + c4*4 == tid*4 by construction
    *reinterpret_cast<float4*>(pooled + (size_t)tid * 4) = o;
}

// ---------------------------------------------------------------------------
// Kernel 2: "unaverage pool" (x4 upsample with the reference's piecewise
// dest->source mapping and masked bilinear taps).
// H=64, stride s=4, dsi=2, max_source=63:
//   lo = 5.5, hi = 2 + 62*4 - 0.5 = 249.5
//   d < 5.5   : src = (d - 2) / 3.5
//   d > 249.5 : src = (d - 249.5) / 3.5 + 62
//   else      : src = (d - 1.5) / 4
// Out-of-range taps contribute 0 (validity mask), matching the reference.
// One thread = one output pixel x 4 channels (float4).
// ---------------------------------------------------------------------------
__device__ __forceinline__ float dest_to_source(float d) {
    if (d < 5.5f)   return (d - 2.0f) * (1.0f / 3.5f);
    if (d > 249.5f) return (d - 249.5f) * (1.0f / 3.5f) + 62.0f;
    return (d - 1.5f) * 0.25f;
}

__global__ __launch_bounds__(256) void up_kernel(const float* __restrict__ pooled,
                                                 float* __restrict__ out) {
    int tid = blockIdx.x * blockDim.x + threadIdx.x;   // 0 .. B*HIN*WIN*16-1
    int c4 = tid & 15;
    int t  = tid >> 4;
    int x = t & (WIN - 1); t >>= 8;
    int y = t & (HIN - 1); t >>= 8;
    int b = t;

    float sr = dest_to_source((float)y);
    float sc = dest_to_source((float)x);
    float r0f = floorf(sr), c0f = floorf(sc);
    int r0 = (int)r0f, c0 = (int)c0f;
    float fr = sr - r0f, fc = sc - c0f;

    const float* pb = pooled + ((size_t)b * HP * WP) * C + c4 * 4;

    float4 p00 = make_float4(0.f, 0.f, 0.f, 0.f);
    float4 p01 = p00, p10 = p00, p11 = p00;

    bool rv0 = (r0 >= 0) & (r0 < HP);
    bool rv1 = (r0 + 1 >= 0) & (r0 + 1 < HP);
    bool cv0 = (c0 >= 0) & (c0 < WP);
    bool cv1 = (c0 + 1 >= 0) & (c0 + 1 < WP);

    if (rv0 & cv0) p00 = *reinterpret_cast<const float4*>(pb + ((size_t)r0 * WP + c0) * C);
    if (rv0 & cv1) p01 = *reinterpret_cast<const float4*>(pb + ((size_t)r0 * WP + c0 + 1) * C);
    if (rv1 & cv0) p10 = *reinterpret_cast<const float4*>(pb + ((size_t)(r0 + 1) * WP + c0) * C);
    if (rv1 & cv1) p11 = *reinterpret_cast<const float4*>(pb + ((size_t)(r0 + 1) * WP + c0 + 1) * C);

    float w00 = (1.0f - fr) * (1.0f - fc);
    float w01 = (1.0f - fr) * fc;
    float w10 = fr * (1.0f - fc);
    float w11 = fr * fc;

    float4 o;
    o.x = p00.x * w00 + p01.x * w01 + p10.x * w10 + p11.x * w11;
    o.y = p00.y * w00 + p01.y * w01 + p10.y * w10 + p11.y * w11;
    o.z = p00.z * w00 + p01.z * w01 + p10.z * w10 + p11.z * w11;
    o.w = p00.w * w00 + p01.w * w01 + p10.w * w10 + p11.w * w11;

    // out index ((b*HIN+y)*WIN+x)*C + c4*4 == tid*4 by construction
    *reinterpret_cast<float4*>(out + (size_t)tid * 4) = o;
}

extern "C" void kernel_launch(void* const* d_in, const int* in_sizes, int n_in,
                              void* d_out, int out_size) {
    const float* in = (const float*)d_in[0];
    float* out = (float*)d_out;

    float* pooled;
    cudaGetSymbolAddress((void**)&pooled, g_pooled);

    {
        int total = B * HP * WP * (C / 4);          // 524288 threads
        pool_kernel<<<total / 256, 256>>>(in, pooled);
    }
    {
        int total = B * HIN * WIN * (C / 4);        // 16.8M threads
        up_kernel<<<total / 256, 256>>>(pooled, out);
    }
}

// round 2
// speedup vs baseline: 1.0624x; 1.0624x over previous
#include <cuda_runtime.h>
#include <cuda_bf16.h>

// Problem constants
#define B    8
#define HIN  256
#define WIN  256
#define CV4  16      // C/4 float4 chunks per pixel (C=64)
#define HP   64
#define WP   64

// 8 MB pooled intermediate (float4 units) — static device scratch
__device__ float4 g_pooled[B * HP * WP * CV4];

__device__ __forceinline__ void acc4(float4& a, const float4 v) {
    a.x += v.x; a.y += v.y; a.z += v.z; a.w += v.w;
}

__device__ __forceinline__ float4 blend2(float4 p, float wp, float4 q, float wq) {
    float4 r;
    r.x = p.x * wp + q.x * wq;
    r.y = p.y * wp + q.y * wq;
    r.z = p.z * wp + q.z * wq;
    r.w = p.w * wp + q.w * wq;
    return r;
}

// ---------------------------------------------------------------------------
// Pool: SAME avg-pool 6x6 stride 4 (pad 1 lo / 1 hi each dim).
// One thread = 4 consecutive ox outputs x one float4 channel chunk.
// The 4 windows cover 18 consecutive columns; the column->window map is
// compile-time unrolled. Interior threads take a predicate-free path.
// ---------------------------------------------------------------------------
template<bool GUARD>
__device__ __forceinline__ void pool_row_accum(const float4* __restrict__ rowp,
                                               int g0, float4* acc) {
    #pragma unroll
    for (int c = 0; c < 18; ++c) {
        float4 v;
        int g = g0 + c;
        if (GUARD && ((unsigned)g >= 256u)) {
            v = make_float4(0.f, 0.f, 0.f, 0.f);
        } else {
            v = __ldg(rowp + (size_t)g * CV4);
        }
        // window j covers local cols [4j, 4j+5]
        if (c <= 5)             acc4(acc[0], v);
        if (c >= 4 && c <= 9)   acc4(acc[1], v);
        if (c >= 8 && c <= 13)  acc4(acc[2], v);
        if (c >= 12)            acc4(acc[3], v);
    }
}

__global__ __launch_bounds__(256) void pool_kernel(const float4* __restrict__ in4) {
    int tid = blockIdx.x * 256 + threadIdx.x;   // B*HP*16*16 = 131072 threads
    int c4  = tid & 15;
    int oxq = (tid >> 4) & 15;
    int oy  = (tid >> 8) & 63;
    int b   = tid >> 14;

    int r0  = oy * 4 - 1;
    int rlo = r0 < 0 ? 0 : r0;
    int rhi = r0 + 6 > 256 ? 256 : r0 + 6;
    int g0  = oxq * 16 - 1;

    float4 acc[4];
    #pragma unroll
    for (int j = 0; j < 4; ++j) acc[j] = make_float4(0.f, 0.f, 0.f, 0.f);

    const float4* base = in4 + ((size_t)b * HIN * WIN) * CV4 + c4;

    if (oxq != 0 && oxq != 15) {
        for (int r = rlo; r < rhi; ++r)
            pool_row_accum<false>(base + (size_t)r * WIN * CV4, g0, acc);
    } else {
        for (int r = rlo; r < rhi; ++r)
            pool_row_accum<true>(base + (size_t)r * WIN * CV4, g0, acc);
    }

    int nr = rhi - rlo;
    float4* outp = g_pooled + (((size_t)b * HP + oy) * WP + oxq * 4) * CV4 + c4;
    #pragma unroll
    for (int j = 0; j < 4; ++j) {
        int ox = oxq * 4 + j;
        int nc = 6 - (ox == 0) - (ox == 63);
        float inv = 1.0f / (float)(nr * nc);
        outp[j * CV4] = make_float4(acc[j].x * inv, acc[j].y * inv,
                                    acc[j].z * inv, acc[j].w * inv);
    }
}

// ---------------------------------------------------------------------------
// Unaverage pool (x4 bilinear-ish upsample with the reference's piecewise
// dest->source mapping). One thread = 4 consecutive x outputs (one dest row y,
// one float4 chunk). Taps needed: pooled cols {k-1, k, k+1} x rows {r0, r0+1}.
// Interior k (2..61): fc weights are compile-time constants -> pure FFMA-imm.
// ---------------------------------------------------------------------------
__device__ __forceinline__ float d2s(float d) {
    if (d < 5.5f)   return (d - 2.0f) * (1.0f / 3.5f);
    if (d > 249.5f) return (d - 249.5f) * (1.0f / 3.5f) + 62.0f;
    return (d - 1.5f) * 0.25f;
}

__global__ __launch_bounds__(256) void up_kernel(float4* __restrict__ out4) {
    int tid = blockIdx.x * 256 + threadIdx.x;   // B*HIN*64*16 = 2097152 threads
    int c4 = tid & 15;
    int k  = (tid >> 4) & 63;
    int y  = (tid >> 10) & 255;
    int b  = tid >> 18;

    // Row mapping (once per thread)
    float sr  = d2s((float)y);
    float r0f = floorf(sr);
    int   r0  = (int)r0f;
    float fr  = sr - r0f;
    bool rv0 = (r0 >= 0);
    bool rv1 = (r0 < HP - 1);

    const float4* pbase = g_pooled + ((size_t)b * HP * WP) * CV4 + c4;
    const float4* rowA  = pbase + (size_t)(rv0 ? r0     : 0) * WP * CV4;
    const float4* rowB  = pbase + (size_t)(rv1 ? r0 + 1 : 0) * WP * CV4;

    const float4 z = make_float4(0.f, 0.f, 0.f, 0.f);
    bool cvl = (k > 0), cvh = (k < WP - 1);

    float4 a_l = (rv0 && cvl) ? __ldg(rowA + (size_t)(k - 1) * CV4) : z;
    float4 a_m =  rv0         ? __ldg(rowA + (size_t)k       * CV4) : z;
    float4 a_h = (rv0 && cvh) ? __ldg(rowA + (size_t)(k + 1) * CV4) : z;
    float4 b_l = (rv1 && cvl) ? __ldg(rowB + (size_t)(k - 1) * CV4) : z;
    float4 b_m =  rv1         ? __ldg(rowB + (size_t)k       * CV4) : z;
    float4 b_h = (rv1 && cvh) ? __ldg(rowB + (size_t)(k + 1) * CV4) : z;

    // Row blend once -> three column taps
    float wr0 = 1.0f - fr;
    float4 tl = blend2(a_l, wr0, b_l, fr);
    float4 tm = blend2(a_m, wr0, b_m, fr);
    float4 th = blend2(a_h, wr0, b_h, fr);

    float4 o0, o1, o2, o3;
    if (k >= 2 && k <= 61) {
        // x = 4k..4k+3: fc = {0.625, 0.875, 0.125, 0.375}, cols (k-1,k),(k-1,k),(k,k+1),(k,k+1)
        o0 = blend2(tl, 0.375f, tm, 0.625f);
        o1 = blend2(tl, 0.125f, tm, 0.875f);
        o2 = blend2(tm, 0.875f, th, 0.125f);
        o3 = blend2(tm, 0.625f, th, 0.375f);
    } else {
        float4 oo[4];
        int x0 = k * 4;
        #pragma unroll
        for (int j = 0; j < 4; ++j) {
            float sc  = d2s((float)(x0 + j));
            float c0f = floorf(sc);
            float fc  = sc - c0f;
            int   sel = (int)c0f - (k - 1);   // 0 or 1
            float4 lo = sel ? tm : tl;
            float4 hi = sel ? th : tm;
            oo[j] = blend2(lo, 1.0f - fc, hi, fc);
        }
        o0 = oo[0]; o1 = oo[1]; o2 = oo[2]; o3 = oo[3];
    }

    float4* op = out4 + (((size_t)b * HIN + y) * WIN + k * 4) * CV4 + c4;
    op[0 * CV4] = o0;
    op[1 * CV4] = o1;
    op[2 * CV4] = o2;
    op[3 * CV4] = o3;
}

extern "C" void kernel_launch(void* const* d_in, const int* in_sizes, int n_in,
                              void* d_out, int out_size) {
    const float4* in4 = (const float4*)d_in[0];
    float4* out4 = (float4*)d_out;

    pool_kernel<<<(B * HP * 16 * 16) / 256, 256>>>(in4);
    up_kernel<<<(B * HIN * 64 * 16) / 256, 256>>>(out4);
}

// round 3
// speedup vs baseline: 1.3884x; 1.3069x over previous
#include <cuda_runtime.h>
#include <cuda_bf16.h>

// Problem constants
#define B    8
#define HIN  256
#define WIN  256
#define CV4  16      // C/4 float4 chunks per pixel (C=64)
#define HP   64
#define WP   64

// Static device scratch (no allocations allowed)
__device__ float4 g_colpool[B * HP * WIN * CV4];   // 33.5 MB: y-pooled sums
__device__ float4 g_pooled [B * HP * WP  * CV4];   //  8  MB: final averages

__device__ __forceinline__ void acc4(float4& a, const float4 v) {
    a.x += v.x; a.y += v.y; a.z += v.z; a.w += v.w;
}

__device__ __forceinline__ float4 blend2(float4 p, float wp, float4 q, float wq) {
    float4 r;
    r.x = p.x * wp + q.x * wq;
    r.y = p.y * wp + q.y * wq;
    r.z = p.z * wp + q.z * wq;
    r.w = p.w * wp + q.w * wq;
    return r;
}

// ---------------------------------------------------------------------------
// Pass 1: column pool (sum over y-window of 6, stride 4, pad 1/1). No divide.
// One thread = one (b, oy, x, c4). Warp reads 512B contiguous per tap.
// ---------------------------------------------------------------------------
__global__ __launch_bounds__(256) void colpool_kernel(const float4* __restrict__ in4) {
    int tid = blockIdx.x * 256 + threadIdx.x;   // B*HP*WIN*CV4 = 2,097,152
    int c4 = tid & 15;
    int x  = (tid >> 4) & 255;
    int oy = (tid >> 12) & 63;
    int b  = tid >> 18;

    int r0 = oy * 4 - 1;
    const float4* p = in4 + (((size_t)b * HIN) * WIN + x) * CV4 + c4;

    float4 s = make_float4(0.f, 0.f, 0.f, 0.f);
    if (oy != 0 && oy != 63) {
        const float4* q = p + (size_t)r0 * WIN * CV4;
        #pragma unroll
        for (int j = 0; j < 6; ++j)
            acc4(s, __ldg(q + (size_t)j * WIN * CV4));
    } else {
        #pragma unroll
        for (int j = 0; j < 6; ++j) {
            int r = r0 + j;
            if ((unsigned)r < 256u)
                acc4(s, __ldg(p + (size_t)r * WIN * CV4));
        }
    }
    // colpool layout: ((b*HP + oy)*WIN + x)*CV4 + c4 == tid
    g_colpool[tid] = s;
}

// ---------------------------------------------------------------------------
// Pass 2: row pool (sum over x-window of 6) + divide by valid count.
// One thread = one (b, oy, ox, c4). Reads stay in L2.
// ---------------------------------------------------------------------------
__global__ __launch_bounds__(256) void rowpool_kernel() {
    int tid = blockIdx.x * 256 + threadIdx.x;   // B*HP*WP*CV4 = 524,288
    int c4 = tid & 15;
    int ox = (tid >> 4) & 63;
    int oy = (tid >> 10) & 63;
    int b  = tid >> 16;

    int cc0 = ox * 4 - 1;
    const float4* p = g_colpool + (((size_t)b * HP + oy) * WIN) * CV4 + c4;

    float4 s = make_float4(0.f, 0.f, 0.f, 0.f);
    if (ox != 0 && ox != 63) {
        const float4* q = p + (size_t)cc0 * CV4;
        #pragma unroll
        for (int j = 0; j < 6; ++j)
            acc4(s, q[(size_t)j * CV4]);
    } else {
        #pragma unroll
        for (int j = 0; j < 6; ++j) {
            int c = cc0 + j;
            if ((unsigned)c < 256u)
                acc4(s, p[(size_t)c * CV4]);
        }
    }

    int nr = 6 - (oy == 0) - (oy == 63);
    int nc = 6 - (ox == 0) - (ox == 63);
    float inv = 1.0f / (float)(nr * nc);
    // pooled layout: ((b*HP+oy)*WP+ox)*CV4 + c4 == tid
    g_pooled[tid] = make_float4(s.x * inv, s.y * inv, s.z * inv, s.w * inv);
}

// ---------------------------------------------------------------------------
// Pass 3: unaverage pool (x4 upsample, reference's piecewise dest->source).
// One thread = 4 consecutive x outputs (one dest row y, one float4 chunk).
// Interior k (2..61): constant fc weights -> pure FFMA-imm.
// ---------------------------------------------------------------------------
__device__ __forceinline__ float d2s(float d) {
    if (d < 5.5f)   return (d - 2.0f) * (1.0f / 3.5f);
    if (d > 249.5f) return (d - 249.5f) * (1.0f / 3.5f) + 62.0f;
    return (d - 1.5f) * 0.25f;
}

__global__ __launch_bounds__(256) void up_kernel(float4* __restrict__ out4) {
    int tid = blockIdx.x * 256 + threadIdx.x;   // B*HIN*64*CV4 = 2,097,152
    int c4 = tid & 15;
    int k  = (tid >> 4) & 63;
    int y  = (tid >> 10) & 255;
    int b  = tid >> 18;

    float sr  = d2s((float)y);
    float r0f = floorf(sr);
    int   r0  = (int)r0f;
    float fr  = sr - r0f;
    bool rv0 = (r0 >= 0);
    bool rv1 = (r0 < HP - 1);

    const float4* pbase = g_pooled + ((size_t)b * HP * WP) * CV4 + c4;
    const float4* rowA  = pbase + (size_t)(rv0 ? r0     : 0) * WP * CV4;
    const float4* rowB  = pbase + (size_t)(rv1 ? r0 + 1 : 0) * WP * CV4;

    const float4 z = make_float4(0.f, 0.f, 0.f, 0.f);
    bool cvl = (k > 0), cvh = (k < WP - 1);

    float4 a_l = (rv0 && cvl) ? __ldg(rowA + (size_t)(k - 1) * CV4) : z;
    float4 a_m =  rv0         ? __ldg(rowA + (size_t)k       * CV4) : z;
    float4 a_h = (rv0 && cvh) ? __ldg(rowA + (size_t)(k + 1) * CV4) : z;
    float4 b_l = (rv1 && cvl) ? __ldg(rowB + (size_t)(k - 1) * CV4) : z;
    float4 b_m =  rv1         ? __ldg(rowB + (size_t)k       * CV4) : z;
    float4 b_h = (rv1 && cvh) ? __ldg(rowB + (size_t)(k + 1) * CV4) : z;

    float wr0 = 1.0f - fr;
    float4 tl = blend2(a_l, wr0, b_l, fr);
    float4 tm = blend2(a_m, wr0, b_m, fr);
    float4 th = blend2(a_h, wr0, b_h, fr);

    float4 o0, o1, o2, o3;
    if (k >= 2 && k <= 61) {
        o0 = blend2(tl, 0.375f, tm, 0.625f);
        o1 = blend2(tl, 0.125f, tm, 0.875f);
        o2 = blend2(tm, 0.875f, th, 0.125f);
        o3 = blend2(tm, 0.625f, th, 0.375f);
    } else {
        float4 oo[4];
        int x0 = k * 4;
        #pragma unroll
        for (int j = 0; j < 4; ++j) {
            float sc  = d2s((float)(x0 + j));
            float c0f = floorf(sc);
            float fc  = sc - c0f;
            int   sel = (int)c0f - (k - 1);   // 0 or 1
            float4 lo = sel ? tm : tl;
            float4 hi = sel ? th : tm;
            oo[j] = blend2(lo, 1.0f - fc, hi, fc);
        }
        o0 = oo[0]; o1 = oo[1]; o2 = oo[2]; o3 = oo[3];
    }

    float4* op = out4 + (((size_t)b * HIN + y) * WIN + k * 4) * CV4 + c4;
    op[0 * CV4] = o0;
    op[1 * CV4] = o1;
    op[2 * CV4] = o2;
    op[3 * CV4] = o3;
}

extern "C" void kernel_launch(void* const* d_in, const int* in_sizes, int n_in,
                              void* d_out, int out_size) {
    const float4* in4 = (const float4*)d_in[0];
    float4* out4 = (float4*)d_out;

    colpool_kernel<<<(B * HP * WIN * CV4) / 256, 256>>>(in4);
    rowpool_kernel<<<(B * HP * WP * CV4) / 256, 256>>>();
    up_kernel<<<(B * HIN * 64 * CV4) / 256, 256>>>(out4);
}